// round 5
// baseline (speedup 1.0000x reference)
#include <cuda_runtime.h>
#include <cstdint>
#include <math.h>

#define NH    16
#define DH    64
#define LSEQ  2048
#define NB    2
#define INNER 1024
#define QK_SCALE 0.125f

// Scratch (__device__ globals; allocation-free rule)
__device__ float g_q[(size_t)NB*NH*LSEQ*DH];   // [b,h,l,dh]
__device__ float g_k[(size_t)NB*NH*LSEQ*DH];
__device__ float g_v[(size_t)NB*NH*LSEQ*DH];
__device__ float g_z[(size_t)NB*LSEQ*INNER];   // [b,l,h*dh]
__device__ float g_wqkvT[(size_t)3072*1024];   // W_qkv^T [n=3072][k=1024]
__device__ float g_woutT[(size_t)1024*1024];   // W_out^T [n=1024][k=1024]

// ---------------------------------------------------------------------------
// PTX helpers (all sm_80-baseline; safe on plain sm_103 target)
// ---------------------------------------------------------------------------
__device__ __forceinline__ void mma8(float d[4], const uint32_t a[4],
                                     const uint32_t b[2]) {
    asm volatile(
        "mma.sync.aligned.m16n8k8.row.col.f32.tf32.tf32.f32 "
        "{%0,%1,%2,%3}, {%4,%5,%6,%7}, {%8,%9}, {%0,%1,%2,%3};"
        : "+f"(d[0]), "+f"(d[1]), "+f"(d[2]), "+f"(d[3])
        : "r"(a[0]), "r"(a[1]), "r"(a[2]), "r"(a[3]),
          "r"(b[0]), "r"(b[1]));
}
__device__ __forceinline__ uint32_t f2tf32(float f) {
    uint32_t o;
    asm("cvt.rna.tf32.f32 %0, %1;" : "=r"(o) : "f"(f));
    return o;
}
__device__ __forceinline__ uint32_t smem_u32(const void* p) {
    uint32_t a;
    asm("{ .reg .u64 t; cvta.to.shared.u64 t, %1; cvt.u32.u64 %0, t; }"
        : "=r"(a) : "l"(p));
    return a;
}
__device__ __forceinline__ void cp_async16(uint32_t dst, const void* src) {
    asm volatile("cp.async.ca.shared.global [%0], [%1], 16;"
                 :: "r"(dst), "l"(src) : "memory");
}
__device__ __forceinline__ void cp_commit() {
    asm volatile("cp.async.commit_group;" ::: "memory");
}
template <int N>
__device__ __forceinline__ void cp_wait() {
    asm volatile("cp.async.wait_group %0;" :: "n"(N) : "memory");
}

// ---------------------------------------------------------------------------
// Transpose: src [R][C] -> dst [C][R]
// ---------------------------------------------------------------------------
__global__ void transpose32(const float* __restrict__ src, float* __restrict__ dst,
                            int R, int C)
{
    __shared__ float t[32][33];
    int c0 = blockIdx.x * 32, r0 = blockIdx.y * 32;
    #pragma unroll
    for (int i = 0; i < 4; i++)
        t[threadIdx.y + i * 8][threadIdx.x] =
            src[(size_t)(r0 + threadIdx.y + i * 8) * C + c0 + threadIdx.x];
    __syncthreads();
    #pragma unroll
    for (int i = 0; i < 4; i++)
        dst[(size_t)(c0 + threadIdx.y + i * 8) * R + r0 + threadIdx.x] =
            t[threadIdx.x][threadIdx.y + i * 8];
}

// ---------------------------------------------------------------------------
// tf32 mma.sync GEMM: C[4096][Ntot] = A[4096][1024] @ Bt[Ntot][1024]^T
// Block 128(M)x64(N), 256 threads = 8 warps (4m x 2n), warp tile 32x32.
// BK=32, cp.async double-buffered. acc = 32 regs -> no spill.
// mode 0: scatter to q/k/v. mode 1: out = C + bias.
// ---------------------------------------------------------------------------
__global__ __launch_bounds__(256) void mma_gemm(const float* __restrict__ A,
                                                const float* __restrict__ Bt,
                                                const float* __restrict__ bias,
                                                float* __restrict__ outp,
                                                int mode)
{
    extern __shared__ uint32_t sh[];
    uint32_t* AsBuf[2] = { sh,               sh + 128 * 36 };
    uint32_t* BsBuf[2] = { sh + 2 * 128 * 36, sh + 2 * 128 * 36 + 64 * 36 };

    const int tid  = threadIdx.x;
    const int lane = tid & 31;
    const int w    = tid >> 5;
    const int wm   = w >> 1;        // 0..3 -> 32-row slab
    const int wn   = w & 1;         // 0..1 -> 32-col slab
    const int g    = lane >> 2;
    const int t    = lane & 3;
    const int m0   = blockIdx.y * 128;
    const int n0   = blockIdx.x * 64;

    float acc[2][4][4];
    #pragma unroll
    for (int mi = 0; mi < 2; mi++)
        #pragma unroll
        for (int nj = 0; nj < 4; nj++)
            #pragma unroll
            for (int r = 0; r < 4; r++) acc[mi][nj][r] = 0.f;

    auto stage = [&](int buf, int kt) {
        uint32_t sa = smem_u32(AsBuf[buf]);
        uint32_t sb = smem_u32(BsBuf[buf]);
        #pragma unroll
        for (int i = 0; i < 4; i++) {        // A tile 128x32 = 1024 float4
            int idx = tid + 256 * i;
            int r = idx >> 3, c = (idx & 7) * 4;
            cp_async16(sa + (uint32_t)(r * 36 + c) * 4,
                       &A[(size_t)(m0 + r) * 1024 + kt * 32 + c]);
        }
        #pragma unroll
        for (int i = 0; i < 2; i++) {        // B tile 64x32 = 512 float4
            int idx = tid + 256 * i;
            int r = idx >> 3, c = (idx & 7) * 4;
            cp_async16(sb + (uint32_t)(r * 36 + c) * 4,
                       &Bt[(size_t)(n0 + r) * 1024 + kt * 32 + c]);
        }
        cp_commit();
    };

    stage(0, 0);

    #pragma unroll 1
    for (int kt = 0; kt < 32; kt++) {
        int cur = kt & 1;
        __syncthreads();                     // all warps done reading buf cur^1
        if (kt + 1 < 32) { stage(cur ^ 1, kt + 1); cp_wait<1>(); }
        else             { cp_wait<0>(); }
        __syncthreads();                     // staged data visible to all

        const uint32_t* Ac = AsBuf[cur];
        const uint32_t* Bc = BsBuf[cur];
        #pragma unroll
        for (int kk = 0; kk < 4; kk++) {
            uint32_t af[2][4], bf[4][2];
            #pragma unroll
            for (int mi = 0; mi < 2; mi++) {
                int rb = wm * 32 + mi * 16;
                af[mi][0] = f2tf32(__uint_as_float(Ac[(rb + g) * 36 + kk * 8 + t]));
                af[mi][1] = f2tf32(__uint_as_float(Ac[(rb + g + 8) * 36 + kk * 8 + t]));
                af[mi][2] = f2tf32(__uint_as_float(Ac[(rb + g) * 36 + kk * 8 + t + 4]));
                af[mi][3] = f2tf32(__uint_as_float(Ac[(rb + g + 8) * 36 + kk * 8 + t + 4]));
            }
            #pragma unroll
            for (int nj = 0; nj < 4; nj++) {
                int nb = wn * 32 + nj * 8;
                bf[nj][0] = f2tf32(__uint_as_float(Bc[(nb + g) * 36 + kk * 8 + t]));
                bf[nj][1] = f2tf32(__uint_as_float(Bc[(nb + g) * 36 + kk * 8 + t + 4]));
            }
            #pragma unroll
            for (int mi = 0; mi < 2; mi++)
                #pragma unroll
                for (int nj = 0; nj < 4; nj++)
                    mma8(acc[mi][nj], af[mi], bf[nj]);
        }
    }

    // Epilogue
    #pragma unroll
    for (int mi = 0; mi < 2; mi++) {
        int r_lo = m0 + wm * 32 + mi * 16 + g;
        int r_hi = r_lo + 8;
        #pragma unroll
        for (int nj = 0; nj < 4; nj++) {
            int n = n0 + wn * 32 + nj * 8 + 2 * t;
            if (mode == 1) {
                float2 o0 = { acc[mi][nj][0] + bias[n], acc[mi][nj][1] + bias[n + 1] };
                float2 o1 = { acc[mi][nj][2] + bias[n], acc[mi][nj][3] + bias[n + 1] };
                *(float2*)&outp[(size_t)r_lo * 1024 + n] = o0;
                *(float2*)&outp[(size_t)r_hi * 1024 + n] = o1;
            } else {
                int three = n >> 10, rem = n & 1023, hh = rem >> 6, dd = rem & 63;
                float* base = (three == 0) ? g_q : (three == 1) ? g_k : g_v;
                int bb_lo = r_lo >> 11, ll_lo = r_lo & 2047;
                int bb_hi = r_hi >> 11, ll_hi = r_hi & 2047;
                float2 o0 = { acc[mi][nj][0], acc[mi][nj][1] };
                float2 o1 = { acc[mi][nj][2], acc[mi][nj][3] };
                *(float2*)&base[(((size_t)(bb_lo * NH + hh) * LSEQ) + ll_lo) * DH + dd] = o0;
                *(float2*)&base[(((size_t)(bb_hi * NH + hh) * LSEQ) + ll_hi) * DH + dd] = o1;
            }
        }
    }
}

// ---------------------------------------------------------------------------
// Attention via mma.sync tf32 (unchanged from round 3 — proven 410us).
// ---------------------------------------------------------------------------
__global__ __launch_bounds__(128) void attn_mma(const float* __restrict__ mask,
                                                float* __restrict__ z)
{
    extern __shared__ uint32_t sh[];
    uint32_t* Ks = sh;                   // [64][68] tf32 bits
    uint32_t* Vs = Ks + 64 * 68;         // [64][72] tf32 bits
    uint32_t* Ps = Vs + 64 * 72;         // [64][68] tf32 bits (also Q staging)
    float*    Ms = (float*)(Ps + 64 * 68);  // [64][68] mask

    const int tid  = threadIdx.x;
    const int lane = tid & 31;
    const int w    = tid >> 5;           // 0..3
    const int g    = lane >> 2;
    const int t    = lane & 3;
    const int qb   = blockIdx.x;
    const int bh   = blockIdx.y;
    const int bb   = bh >> 4, hh = bh & 15;
    const int q0   = qb * 64;
    const int rw   = w * 16;

    const float* qp = g_q + ((size_t)bh * LSEQ + q0) * DH;
    const float* kp = g_k + (size_t)bh * LSEQ * DH;
    const float* vp = g_v + (size_t)bh * LSEQ * DH;

    #pragma unroll
    for (int i = 0; i < 8; i++) {
        int s = tid + 128 * i;
        int r = s >> 4, c = (s & 15) * 4;
        *(float4*)&Ps[r * 68 + c] = *(const float4*)&qp[r * 64 + c];
    }
    __syncthreads();

    uint32_t qa[8][4];
    {
        const float* Pf = (const float*)Ps;
        #pragma unroll
        for (int kk = 0; kk < 8; kk++) {
            qa[kk][0] = f2tf32(QK_SCALE * Pf[(rw + g) * 68 + kk * 8 + t]);
            qa[kk][1] = f2tf32(QK_SCALE * Pf[(rw + g + 8) * 68 + kk * 8 + t]);
            qa[kk][2] = f2tf32(QK_SCALE * Pf[(rw + g) * 68 + kk * 8 + t + 4]);
            qa[kk][3] = f2tf32(QK_SCALE * Pf[(rw + g + 8) * 68 + kk * 8 + t + 4]);
        }
    }

    float zacc[8][4];
    #pragma unroll
    for (int j = 0; j < 8; j++)
        #pragma unroll
        for (int r = 0; r < 4; r++) zacc[j][r] = 0.f;
    float sa_lo = 0.f, sa_hi = 0.f, sk_lo = 0.f, sk_hi = 0.f;

    #pragma unroll 1
    for (int jt = 0; jt < LSEQ / 64; jt++) {
        __syncthreads();
        #pragma unroll
        for (int i = 0; i < 8; i++) {
            int s = tid + 128 * i;
            int r = s >> 4, c = (s & 15) * 4;
            float4 k4 = *(const float4*)&kp[(size_t)(jt * 64 + r) * 64 + c];
            uint4 tk = { f2tf32(k4.x), f2tf32(k4.y), f2tf32(k4.z), f2tf32(k4.w) };
            *(uint4*)&Ks[r * 68 + c] = tk;
            float4 v4 = *(const float4*)&vp[(size_t)(jt * 64 + r) * 64 + c];
            uint4 tv = { f2tf32(v4.x), f2tf32(v4.y), f2tf32(v4.z), f2tf32(v4.w) };
            *(uint4*)&Vs[r * 72 + c] = tv;
            float4 m4 = *(const float4*)&mask[((size_t)bb * LSEQ + q0 + r) * LSEQ + jt * 64 + c];
            *(float4*)&Ms[r * 68 + c] = m4;
        }
        __syncthreads();

        float sacc[8][4];
        #pragma unroll
        for (int j = 0; j < 8; j++)
            #pragma unroll
            for (int r = 0; r < 4; r++) sacc[j][r] = 0.f;
        #pragma unroll
        for (int kk = 0; kk < 8; kk++) {
            #pragma unroll
            for (int j = 0; j < 8; j++) {
                uint32_t bf[2];
                bf[0] = Ks[(j * 8 + g) * 68 + kk * 8 + t];
                bf[1] = Ks[(j * 8 + g) * 68 + kk * 8 + t + 4];
                mma8(sacc[j], qa[kk], bf);
            }
        }

        #pragma unroll
        for (int j = 0; j < 8; j++) {
            float p0 = __expf(sacc[j][0]);
            float p1 = __expf(sacc[j][1]);
            float p2 = __expf(sacc[j][2]);
            float p3 = __expf(sacc[j][3]);
            float2 mlo = *(const float2*)&Ms[(rw + g) * 68 + j * 8 + 2 * t];
            float2 mhi = *(const float2*)&Ms[(rw + g + 8) * 68 + j * 8 + 2 * t];
            float w0 = p0 * mlo.x, w1 = p1 * mlo.y;
            float w2 = p2 * mhi.x, w3 = p3 * mhi.y;
            sa_lo += p0 + p1;  sa_hi += p2 + p3;
            sk_lo += w0 + w1;  sk_hi += w2 + w3;
            uint2 plo = { f2tf32(w0), f2tf32(w1) };
            uint2 phi = { f2tf32(w2), f2tf32(w3) };
            *(uint2*)&Ps[(rw + g) * 68 + j * 8 + 2 * t] = plo;
            *(uint2*)&Ps[(rw + g + 8) * 68 + j * 8 + 2 * t] = phi;
        }
        __syncthreads();

        #pragma unroll
        for (int kk = 0; kk < 8; kk++) {
            uint32_t pa[4];
            pa[0] = Ps[(rw + g) * 68 + kk * 8 + t];
            pa[1] = Ps[(rw + g + 8) * 68 + kk * 8 + t];
            pa[2] = Ps[(rw + g) * 68 + kk * 8 + t + 4];
            pa[3] = Ps[(rw + g + 8) * 68 + kk * 8 + t + 4];
            #pragma unroll
            for (int j = 0; j < 8; j++) {
                uint32_t bf[2];
                bf[0] = Vs[(kk * 8 + t) * 72 + j * 8 + g];
                bf[1] = Vs[(kk * 8 + t + 4) * 72 + j * 8 + g];
                mma8(zacc[j], pa, bf);
            }
        }
    }

    #pragma unroll
    for (int d = 1; d <= 2; d <<= 1) {
        sa_lo += __shfl_xor_sync(0xffffffffu, sa_lo, d);
        sa_hi += __shfl_xor_sync(0xffffffffu, sa_hi, d);
        sk_lo += __shfl_xor_sync(0xffffffffu, sk_lo, d);
        sk_hi += __shfl_xor_sync(0xffffffffu, sk_hi, d);
    }
    float inv_lo = 1.f / (sk_lo + 1e-10f * sa_lo);
    float inv_hi = 1.f / (sk_hi + 1e-10f * sa_hi);

    size_t row_lo = (size_t)bb * LSEQ + q0 + rw + g;
    size_t row_hi = row_lo + 8;
    #pragma unroll
    for (int j = 0; j < 8; j++) {
        int dh = hh * 64 + j * 8 + 2 * t;
        float2 o0 = { zacc[j][0] * inv_lo, zacc[j][1] * inv_lo };
        float2 o1 = { zacc[j][2] * inv_hi, zacc[j][3] * inv_hi };
        *(float2*)&z[row_lo * INNER + dh] = o0;
        *(float2*)&z[row_hi * INNER + dh] = o1;
    }
}

// ---------------------------------------------------------------------------
extern "C" void kernel_launch(void* const* d_in, const int* in_sizes, int n_in,
                              void* d_out, int out_size)
{
    const float* x     = (const float*)d_in[0];  // [2,2048,1024]
    const float* mask  = (const float*)d_in[1];  // [2,2048,2048]
    const float* W_qkv = (const float*)d_in[2];  // [1024,3072]
    const float* W_out = (const float*)d_in[3];  // [1024,1024]
    const float* b_out = (const float*)d_in[4];  // [1024]
    float* out = (float*)d_out;

    // Transpose weights to [n][k] for the col-major B operand
    {
        dim3 blk(32, 8);
        transpose32<<<dim3(3072 / 32, 1024 / 32), blk>>>(W_qkv, g_wqkvT, 1024, 3072);
        transpose32<<<dim3(1024 / 32, 1024 / 32), blk>>>(W_out, g_woutT, 1024, 1024);
    }

    const int gemm_smem = (2 * 128 * 36 + 2 * 64 * 36) * 4;   // 55296 B
    cudaFuncSetAttribute(mma_gemm, cudaFuncAttributeMaxDynamicSharedMemorySize, gemm_smem);

    // QKV projection -> scatter to q/k/v
    mma_gemm<<<dim3(3072 / 64, 4096 / 128), 256, gemm_smem>>>(
        x, g_wqkvT, nullptr, nullptr, 0);

    // Attention
    const int attn_smem = (64 * 68 * 3 + 64 * 72) * 4;  // 70656 B
    cudaFuncSetAttribute(attn_mma, cudaFuncAttributeMaxDynamicSharedMemorySize, attn_smem);
    attn_mma<<<dim3(LSEQ / 64, NB * NH), 128, attn_smem>>>(mask, g_z);

    // Output projection + bias
    mma_gemm<<<dim3(1024 / 64, 4096 / 128), 256, gemm_smem>>>(
        g_z, g_woutT, b_out, out, 1);
}

// round 9
// speedup vs baseline: 1.9548x; 1.9548x over previous
#include <cuda_runtime.h>
#include <cstdint>
#include <math.h>

#define NH    16
#define DH    64
#define LSEQ  2048
#define NB    2
#define INNER 1024
#define QK_SCALE 0.125f

// Scratch (__device__ globals; allocation-free rule)
__device__ float g_q[(size_t)NB*NH*LSEQ*DH];   // [b,h,l,dh]
__device__ float g_k[(size_t)NB*NH*LSEQ*DH];
__device__ float g_v[(size_t)NB*NH*LSEQ*DH];
__device__ float g_z[(size_t)NB*LSEQ*INNER];   // [b,l,h*dh]

// ---------------------------------------------------------------------------
// PTX helpers (sm_80-baseline; safe on plain sm_103 target)
// ---------------------------------------------------------------------------
__device__ __forceinline__ void mma8(float d[4], const uint32_t a[4],
                                     const uint32_t b[2]) {
    asm volatile(
        "mma.sync.aligned.m16n8k8.row.col.f32.tf32.tf32.f32 "
        "{%0,%1,%2,%3}, {%4,%5,%6,%7}, {%8,%9}, {%0,%1,%2,%3};"
        : "+f"(d[0]), "+f"(d[1]), "+f"(d[2]), "+f"(d[3])
        : "r"(a[0]), "r"(a[1]), "r"(a[2]), "r"(a[3]),
          "r"(b[0]), "r"(b[1]));
}
__device__ __forceinline__ uint32_t f2tf32(float f) {
    uint32_t o;
    asm("cvt.rna.tf32.f32 %0, %1;" : "=r"(o) : "f"(f));
    return o;
}

// ---------------------------------------------------------------------------
// Projection GEMM cloned from the proven attn loop shape.
// C[4096][Ncols] = A[4096][1024] @ W[1024][Ncols]  (W in NATIVE layout)
// 128 threads = 4 warps; block tile 64(M) x 64(N); K-tiles of 64.
// A staged like Q/K (stride 68); W staged like V (stride 72, [k][n]).
// mode 0: scatter C to q/k/v (Ncols=3072). mode 1: C + bias -> out.
// ---------------------------------------------------------------------------
__global__ __launch_bounds__(128) void gemm64(const float* __restrict__ A,
                                              const float* __restrict__ W,
                                              const float* __restrict__ bias,
                                              float* __restrict__ outp,
                                              int Ncols, int mode)
{
    extern __shared__ uint32_t sh[];
    uint32_t* As = sh;              // [64][68] tf32 bits (A tile, row=m, col=k)
    uint32_t* Bs = sh + 64 * 68;    // [64][72] tf32 bits (W tile, row=k, col=n)

    const int tid  = threadIdx.x;
    const int lane = tid & 31;
    const int w    = tid >> 5;      // 0..3
    const int g    = lane >> 2;
    const int t    = lane & 3;
    const int m0   = blockIdx.y * 64;
    const int n0   = blockIdx.x * 64;
    const int rw   = w * 16;        // warp's 16-row slab within M tile

    float acc[8][4];
    #pragma unroll
    for (int j = 0; j < 8; j++)
        #pragma unroll
        for (int r = 0; r < 4; r++) acc[j][r] = 0.f;

    #pragma unroll 1
    for (int kt = 0; kt < 16; kt++) {
        __syncthreads();
        // Stage A (64x64) and W (64x64) tiles, cvt to tf32 (attn staging pattern)
        #pragma unroll
        for (int i = 0; i < 8; i++) {
            int s = tid + 128 * i;
            int r = s >> 4, c = (s & 15) * 4;
            float4 a4 = *(const float4*)&A[(size_t)(m0 + r) * 1024 + kt * 64 + c];
            uint4 ta = { f2tf32(a4.x), f2tf32(a4.y), f2tf32(a4.z), f2tf32(a4.w) };
            *(uint4*)&As[r * 68 + c] = ta;
            float4 w4 = *(const float4*)&W[(size_t)(kt * 64 + r) * Ncols + n0 + c];
            uint4 tw = { f2tf32(w4.x), f2tf32(w4.y), f2tf32(w4.z), f2tf32(w4.w) };
            *(uint4*)&Bs[r * 72 + c] = tw;
        }
        __syncthreads();

        // acc += A_tile @ W_tile  (exact PV-loop fragment pattern)
        #pragma unroll
        for (int kk = 0; kk < 8; kk++) {
            uint32_t af[4];
            af[0] = As[(rw + g) * 68 + kk * 8 + t];
            af[1] = As[(rw + g + 8) * 68 + kk * 8 + t];
            af[2] = As[(rw + g) * 68 + kk * 8 + t + 4];
            af[3] = As[(rw + g + 8) * 68 + kk * 8 + t + 4];
            #pragma unroll
            for (int j = 0; j < 8; j++) {
                uint32_t bf[2];
                bf[0] = Bs[(kk * 8 + t) * 72 + j * 8 + g];
                bf[1] = Bs[(kk * 8 + t + 4) * 72 + j * 8 + g];
                mma8(acc[j], af, bf);
            }
        }
    }

    // Epilogue (same fragment->row/col mapping as attn's z write)
    int r_lo = m0 + rw + g;
    int r_hi = r_lo + 8;
    #pragma unroll
    for (int j = 0; j < 8; j++) {
        int n = n0 + j * 8 + 2 * t;
        if (mode == 1) {
            float2 o0 = { acc[j][0] + bias[n], acc[j][1] + bias[n + 1] };
            float2 o1 = { acc[j][2] + bias[n], acc[j][3] + bias[n + 1] };
            *(float2*)&outp[(size_t)r_lo * 1024 + n] = o0;
            *(float2*)&outp[(size_t)r_hi * 1024 + n] = o1;
        } else {
            int three = n >> 10, rem = n & 1023, hh = rem >> 6, dd = rem & 63;
            float* base = (three == 0) ? g_q : (three == 1) ? g_k : g_v;
            int bb_lo = r_lo >> 11, ll_lo = r_lo & 2047;
            int bb_hi = r_hi >> 11, ll_hi = r_hi & 2047;
            float2 o0 = { acc[j][0], acc[j][1] };
            float2 o1 = { acc[j][2], acc[j][3] };
            *(float2*)&base[(((size_t)(bb_lo * NH + hh) * LSEQ) + ll_lo) * DH + dd] = o0;
            *(float2*)&base[(((size_t)(bb_hi * NH + hh) * LSEQ) + ll_hi) * DH + dd] = o1;
        }
    }
}

// ---------------------------------------------------------------------------
// Attention via mma.sync tf32 (unchanged — proven 416us / ~83 TF/s).
// ---------------------------------------------------------------------------
__global__ __launch_bounds__(128) void attn_mma(const float* __restrict__ mask,
                                                float* __restrict__ z)
{
    extern __shared__ uint32_t sh[];
    uint32_t* Ks = sh;                   // [64][68] tf32 bits
    uint32_t* Vs = Ks + 64 * 68;         // [64][72] tf32 bits
    uint32_t* Ps = Vs + 64 * 72;         // [64][68] tf32 bits (also Q staging)
    float*    Ms = (float*)(Ps + 64 * 68);  // [64][68] mask

    const int tid  = threadIdx.x;
    const int lane = tid & 31;
    const int w    = tid >> 5;           // 0..3
    const int g    = lane >> 2;
    const int t    = lane & 3;
    const int qb   = blockIdx.x;
    const int bh   = blockIdx.y;
    const int bb   = bh >> 4, hh = bh & 15;
    const int q0   = qb * 64;
    const int rw   = w * 16;

    const float* qp = g_q + ((size_t)bh * LSEQ + q0) * DH;
    const float* kp = g_k + (size_t)bh * LSEQ * DH;
    const float* vp = g_v + (size_t)bh * LSEQ * DH;

    #pragma unroll
    for (int i = 0; i < 8; i++) {
        int s = tid + 128 * i;
        int r = s >> 4, c = (s & 15) * 4;
        *(float4*)&Ps[r * 68 + c] = *(const float4*)&qp[r * 64 + c];
    }
    __syncthreads();

    uint32_t qa[8][4];
    {
        const float* Pf = (const float*)Ps;
        #pragma unroll
        for (int kk = 0; kk < 8; kk++) {
            qa[kk][0] = f2tf32(QK_SCALE * Pf[(rw + g) * 68 + kk * 8 + t]);
            qa[kk][1] = f2tf32(QK_SCALE * Pf[(rw + g + 8) * 68 + kk * 8 + t]);
            qa[kk][2] = f2tf32(QK_SCALE * Pf[(rw + g) * 68 + kk * 8 + t + 4]);
            qa[kk][3] = f2tf32(QK_SCALE * Pf[(rw + g + 8) * 68 + kk * 8 + t + 4]);
        }
    }

    float zacc[8][4];
    #pragma unroll
    for (int j = 0; j < 8; j++)
        #pragma unroll
        for (int r = 0; r < 4; r++) zacc[j][r] = 0.f;
    float sa_lo = 0.f, sa_hi = 0.f, sk_lo = 0.f, sk_hi = 0.f;

    #pragma unroll 1
    for (int jt = 0; jt < LSEQ / 64; jt++) {
        __syncthreads();
        #pragma unroll
        for (int i = 0; i < 8; i++) {
            int s = tid + 128 * i;
            int r = s >> 4, c = (s & 15) * 4;
            float4 k4 = *(const float4*)&kp[(size_t)(jt * 64 + r) * 64 + c];
            uint4 tk = { f2tf32(k4.x), f2tf32(k4.y), f2tf32(k4.z), f2tf32(k4.w) };
            *(uint4*)&Ks[r * 68 + c] = tk;
            float4 v4 = *(const float4*)&vp[(size_t)(jt * 64 + r) * 64 + c];
            uint4 tv = { f2tf32(v4.x), f2tf32(v4.y), f2tf32(v4.z), f2tf32(v4.w) };
            *(uint4*)&Vs[r * 72 + c] = tv;
            float4 m4 = *(const float4*)&mask[((size_t)bb * LSEQ + q0 + r) * LSEQ + jt * 64 + c];
            *(float4*)&Ms[r * 68 + c] = m4;
        }
        __syncthreads();

        float sacc[8][4];
        #pragma unroll
        for (int j = 0; j < 8; j++)
            #pragma unroll
            for (int r = 0; r < 4; r++) sacc[j][r] = 0.f;
        #pragma unroll
        for (int kk = 0; kk < 8; kk++) {
            #pragma unroll
            for (int j = 0; j < 8; j++) {
                uint32_t bf[2];
                bf[0] = Ks[(j * 8 + g) * 68 + kk * 8 + t];
                bf[1] = Ks[(j * 8 + g) * 68 + kk * 8 + t + 4];
                mma8(sacc[j], qa[kk], bf);
            }
        }

        #pragma unroll
        for (int j = 0; j < 8; j++) {
            float p0 = __expf(sacc[j][0]);
            float p1 = __expf(sacc[j][1]);
            float p2 = __expf(sacc[j][2]);
            float p3 = __expf(sacc[j][3]);
            float2 mlo = *(const float2*)&Ms[(rw + g) * 68 + j * 8 + 2 * t];
            float2 mhi = *(const float2*)&Ms[(rw + g + 8) * 68 + j * 8 + 2 * t];
            float w0 = p0 * mlo.x, w1 = p1 * mlo.y;
            float w2 = p2 * mhi.x, w3 = p3 * mhi.y;
            sa_lo += p0 + p1;  sa_hi += p2 + p3;
            sk_lo += w0 + w1;  sk_hi += w2 + w3;
            uint2 plo = { f2tf32(w0), f2tf32(w1) };
            uint2 phi = { f2tf32(w2), f2tf32(w3) };
            *(uint2*)&Ps[(rw + g) * 68 + j * 8 + 2 * t] = plo;
            *(uint2*)&Ps[(rw + g + 8) * 68 + j * 8 + 2 * t] = phi;
        }
        __syncthreads();

        #pragma unroll
        for (int kk = 0; kk < 8; kk++) {
            uint32_t pa[4];
            pa[0] = Ps[(rw + g) * 68 + kk * 8 + t];
            pa[1] = Ps[(rw + g + 8) * 68 + kk * 8 + t];
            pa[2] = Ps[(rw + g) * 68 + kk * 8 + t + 4];
            pa[3] = Ps[(rw + g + 8) * 68 + kk * 8 + t + 4];
            #pragma unroll
            for (int j = 0; j < 8; j++) {
                uint32_t bf[2];
                bf[0] = Vs[(kk * 8 + t) * 72 + j * 8 + g];
                bf[1] = Vs[(kk * 8 + t + 4) * 72 + j * 8 + g];
                mma8(zacc[j], pa, bf);
            }
        }
    }

    #pragma unroll
    for (int d = 1; d <= 2; d <<= 1) {
        sa_lo += __shfl_xor_sync(0xffffffffu, sa_lo, d);
        sa_hi += __shfl_xor_sync(0xffffffffu, sa_hi, d);
        sk_lo += __shfl_xor_sync(0xffffffffu, sk_lo, d);
        sk_hi += __shfl_xor_sync(0xffffffffu, sk_hi, d);
    }
    float inv_lo = 1.f / (sk_lo + 1e-10f * sa_lo);
    float inv_hi = 1.f / (sk_hi + 1e-10f * sa_hi);

    size_t row_lo = (size_t)bb * LSEQ + q0 + rw + g;
    size_t row_hi = row_lo + 8;
    #pragma unroll
    for (int j = 0; j < 8; j++) {
        int dh = hh * 64 + j * 8 + 2 * t;
        float2 o0 = { zacc[j][0] * inv_lo, zacc[j][1] * inv_lo };
        float2 o1 = { zacc[j][2] * inv_hi, zacc[j][3] * inv_hi };
        *(float2*)&z[row_lo * INNER + dh] = o0;
        *(float2*)&z[row_hi * INNER + dh] = o1;
    }
}

// ---------------------------------------------------------------------------
extern "C" void kernel_launch(void* const* d_in, const int* in_sizes, int n_in,
                              void* d_out, int out_size)
{
    const float* x     = (const float*)d_in[0];  // [2,2048,1024]
    const float* mask  = (const float*)d_in[1];  // [2,2048,2048]
    const float* W_qkv = (const float*)d_in[2];  // [1024,3072]
    const float* W_out = (const float*)d_in[3];  // [1024,1024]
    const float* b_out = (const float*)d_in[4];  // [1024]
    float* out = (float*)d_out;

    const int gemm_smem = (64 * 68 + 64 * 72) * 4;   // 35840 B
    cudaFuncSetAttribute(gemm64, cudaFuncAttributeMaxDynamicSharedMemorySize, gemm_smem);

    // QKV projection -> scatter to q/k/v (W in native [k][n] layout)
    gemm64<<<dim3(3072 / 64, 4096 / 64), 128, gemm_smem>>>(
        x, W_qkv, nullptr, nullptr, 3072, 0);

    // Attention
    const int attn_smem = (64 * 68 * 3 + 64 * 72) * 4;  // 70656 B
    cudaFuncSetAttribute(attn_mma, cudaFuncAttributeMaxDynamicSharedMemorySize, attn_smem);
    attn_mma<<<dim3(LSEQ / 64, NB * NH), 128, attn_smem>>>(mask, g_z);

    // Output projection + bias
    gemm64<<<dim3(1024 / 64, 4096 / 64), 128, gemm_smem>>>(
        g_z, W_out, b_out, out, 1024, 1);
}

// round 10
// speedup vs baseline: 2.1024x; 1.0755x over previous
#include <cuda_runtime.h>
#include <cuda_fp16.h>
#include <cstdint>
#include <math.h>

#define NH    16
#define DH    64
#define LSEQ  2048
#define NB    2
#define INNER 1024
#define QK_SCALE 0.125f

// Scratch (__device__ globals; allocation-free rule)
__device__ float g_q[(size_t)NB*NH*LSEQ*DH];   // [b,h,l,dh]
__device__ float g_k[(size_t)NB*NH*LSEQ*DH];
__device__ float g_v[(size_t)NB*NH*LSEQ*DH];
__device__ float g_z[(size_t)NB*LSEQ*INNER];   // [b,l,h*dh]

// ---------------------------------------------------------------------------
// PTX helpers (sm_80-baseline; safe on plain sm_103 target)
// ---------------------------------------------------------------------------
__device__ __forceinline__ void mma16(float d[4], const uint32_t a[4],
                                      const uint32_t b[2]) {
    asm volatile(
        "mma.sync.aligned.m16n8k16.row.col.f32.f16.f16.f32 "
        "{%0,%1,%2,%3}, {%4,%5,%6,%7}, {%8,%9}, {%0,%1,%2,%3};"
        : "+f"(d[0]), "+f"(d[1]), "+f"(d[2]), "+f"(d[3])
        : "r"(a[0]), "r"(a[1]), "r"(a[2]), "r"(a[3]),
          "r"(b[0]), "r"(b[1]));
}
// pack2(lo, hi): half2 with .x = lo (lower half / lower k index)
__device__ __forceinline__ uint32_t pack2(float lo, float hi) {
    __half2 h = __floats2half2_rn(lo, hi);
    return *(uint32_t*)&h;
}

// ---------------------------------------------------------------------------
// fp16 mma GEMM: C[4096][Ncols] = A[4096][1024] @ W[1024][Ncols] (W native)
// 128 threads = 4 warps; block tile 64(M) x 64(N); K-tile 128.
// As2: [64 m][68] half2 along k.  Bs2: [64 kpair][68] half2 = {W[2k][n],W[2k+1][n]}.
// mode 0: scatter C to q/k/v. mode 1: C + bias -> out.
// ---------------------------------------------------------------------------
__global__ __launch_bounds__(128) void gemm64h(const float* __restrict__ A,
                                               const float* __restrict__ W,
                                               const float* __restrict__ bias,
                                               float* __restrict__ outp,
                                               int Ncols, int mode)
{
    extern __shared__ uint32_t sh[];
    uint32_t* As2 = sh;              // [64][68] u32 (half2 pairs along k)
    uint32_t* Bs2 = sh + 64 * 68;    // [64][68] u32 (half2 = two k-rows)

    const int tid  = threadIdx.x;
    const int lane = tid & 31;
    const int w    = tid >> 5;      // 0..3
    const int g    = lane >> 2;
    const int t    = lane & 3;
    const int m0   = blockIdx.y * 64;
    const int n0   = blockIdx.x * 64;
    const int rw   = w * 16;

    float acc[8][4];
    #pragma unroll
    for (int j = 0; j < 8; j++)
        #pragma unroll
        for (int r = 0; r < 4; r++) acc[j][r] = 0.f;

    #pragma unroll 1
    for (int kt = 0; kt < 8; kt++) {
        __syncthreads();
        // Stage A 64x128 (fp32 -> half2 pairs along k)
        #pragma unroll
        for (int i = 0; i < 16; i++) {
            int idx = tid + 128 * i;
            int r = idx >> 5, c = (idx & 31) * 4;
            float4 a4 = *(const float4*)&A[(size_t)(m0 + r) * 1024 + kt * 128 + c];
            uint2 p = { pack2(a4.x, a4.y), pack2(a4.z, a4.w) };
            *(uint2*)&As2[r * 68 + (c >> 1)] = p;
        }
        // Stage B 128x64: pack rows 2k,2k+1 into half2
        #pragma unroll
        for (int i = 0; i < 8; i++) {
            int idx = tid + 128 * i;
            int kp = idx >> 4, nc = (idx & 15) * 4;
            const float* wr = W + (size_t)(kt * 128 + 2 * kp) * Ncols + n0 + nc;
            float4 e = *(const float4*)wr;
            float4 o = *(const float4*)(wr + Ncols);
            uint4 p = { pack2(e.x, o.x), pack2(e.y, o.y),
                        pack2(e.z, o.z), pack2(e.w, o.w) };
            *(uint4*)&Bs2[kp * 68 + nc] = p;
        }
        __syncthreads();

        #pragma unroll
        for (int ks = 0; ks < 8; ks++) {
            uint32_t af[4];
            af[0] = As2[(rw + g) * 68 + ks * 8 + t];
            af[1] = As2[(rw + g + 8) * 68 + ks * 8 + t];
            af[2] = As2[(rw + g) * 68 + ks * 8 + t + 4];
            af[3] = As2[(rw + g + 8) * 68 + ks * 8 + t + 4];
            #pragma unroll
            for (int j = 0; j < 8; j++) {
                uint32_t bf[2];
                bf[0] = Bs2[(ks * 8 + t) * 68 + j * 8 + g];
                bf[1] = Bs2[(ks * 8 + t + 4) * 68 + j * 8 + g];
                mma16(acc[j], af, bf);
            }
        }
    }

    // Epilogue (same fragment->row/col mapping as before)
    int r_lo = m0 + rw + g;
    int r_hi = r_lo + 8;
    #pragma unroll
    for (int j = 0; j < 8; j++) {
        int n = n0 + j * 8 + 2 * t;
        if (mode == 1) {
            float2 o0 = { acc[j][0] + bias[n], acc[j][1] + bias[n + 1] };
            float2 o1 = { acc[j][2] + bias[n], acc[j][3] + bias[n + 1] };
            *(float2*)&outp[(size_t)r_lo * 1024 + n] = o0;
            *(float2*)&outp[(size_t)r_hi * 1024 + n] = o1;
        } else {
            int three = n >> 10, rem = n & 1023, hh = rem >> 6, dd = rem & 63;
            float* base = (three == 0) ? g_q : (three == 1) ? g_k : g_v;
            int bb_lo = r_lo >> 11, ll_lo = r_lo & 2047;
            int bb_hi = r_hi >> 11, ll_hi = r_hi & 2047;
            float2 o0 = { acc[j][0], acc[j][1] };
            float2 o1 = { acc[j][2], acc[j][3] };
            *(float2*)&base[(((size_t)(bb_lo * NH + hh) * LSEQ) + ll_lo) * DH + dd] = o0;
            *(float2*)&base[(((size_t)(bb_hi * NH + hh) * LSEQ) + ll_hi) * DH + dd] = o1;
        }
    }
}

// ---------------------------------------------------------------------------
// Attention via fp16 mma m16n8k16. BM=64, 128 threads = 4 warps.
// No-max exact softmax: p = exp(s); z = (p*mask)@V / (sum(p*mask)+eps*sum(p)).
// Q fragments built directly from gmem (scale folded). P is warp-private.
// ---------------------------------------------------------------------------
__global__ __launch_bounds__(128) void attn_mma(const float* __restrict__ mask,
                                                float* __restrict__ z)
{
    extern __shared__ uint32_t sh[];
    uint32_t* Ks2 = sh;                    // [64 seq][36] half2 along dh
    uint32_t* Vs2 = Ks2 + 64 * 36;         // [32 seqpair][68] half2 = two seq rows
    uint32_t* Ps2 = Vs2 + 32 * 68;         // [64 q][36] half2 along seq
    float*    Ms  = (float*)(Ps2 + 64 * 36); // [64 q][68] fp32 mask

    const int tid  = threadIdx.x;
    const int lane = tid & 31;
    const int w    = tid >> 5;
    const int g    = lane >> 2;
    const int t    = lane & 3;
    const int qb   = blockIdx.x;
    const int bh   = blockIdx.y;
    const int bb   = bh >> 4, hh = bh & 15;
    const int q0   = qb * 64;
    const int rw   = w * 16;

    const float* qp = g_q + ((size_t)bh * LSEQ + q0) * DH;
    const float* kp = g_k + (size_t)bh * LSEQ * DH;
    const float* vp = g_v + (size_t)bh * LSEQ * DH;

    // Q fragments direct from gmem, scale folded. 4 k16-steps cover dh=64.
    uint32_t qa[4][4];
    #pragma unroll
    for (int ks = 0; ks < 4; ks++) {
        const float* q_lo = qp + (rw + g) * 64 + ks * 16 + 2 * t;
        const float* q_hi = q_lo + 8 * 64;
        float2 a = *(const float2*)q_lo;
        float2 b = *(const float2*)q_hi;
        float2 c = *(const float2*)(q_lo + 8);
        float2 d = *(const float2*)(q_hi + 8);
        qa[ks][0] = pack2(QK_SCALE * a.x, QK_SCALE * a.y);
        qa[ks][1] = pack2(QK_SCALE * b.x, QK_SCALE * b.y);
        qa[ks][2] = pack2(QK_SCALE * c.x, QK_SCALE * c.y);
        qa[ks][3] = pack2(QK_SCALE * d.x, QK_SCALE * d.y);
    }

    float zacc[8][4];
    #pragma unroll
    for (int j = 0; j < 8; j++)
        #pragma unroll
        for (int r = 0; r < 4; r++) zacc[j][r] = 0.f;
    float sa_lo = 0.f, sa_hi = 0.f, sk_lo = 0.f, sk_hi = 0.f;

    #pragma unroll 1
    for (int jt = 0; jt < LSEQ / 64; jt++) {
        __syncthreads();   // prior PV reads of Vs2 complete before restaging
        // Stage K 64x64 (half2 along dh)
        #pragma unroll
        for (int i = 0; i < 8; i++) {
            int idx = tid + 128 * i;
            int r = idx >> 4, c = (idx & 15) * 4;
            float4 k4 = *(const float4*)&kp[(size_t)(jt * 64 + r) * 64 + c];
            uint2 p = { pack2(k4.x, k4.y), pack2(k4.z, k4.w) };
            *(uint2*)&Ks2[r * 36 + (c >> 1)] = p;
        }
        // Stage V 64x64: pack seq rows 2s,2s+1 into half2
        #pragma unroll
        for (int i = 0; i < 4; i++) {
            int idx = tid + 128 * i;
            int s = idx >> 4, d = (idx & 15) * 4;
            const float* vr = vp + (size_t)(jt * 64 + 2 * s) * 64 + d;
            float4 e = *(const float4*)vr;
            float4 o = *(const float4*)(vr + 64);
            uint4 p = { pack2(e.x, o.x), pack2(e.y, o.y),
                        pack2(e.z, o.z), pack2(e.w, o.w) };
            *(uint4*)&Vs2[s * 68 + d] = p;
        }
        // Stage mask (fp32)
        #pragma unroll
        for (int i = 0; i < 8; i++) {
            int idx = tid + 128 * i;
            int r = idx >> 4, c = (idx & 15) * 4;
            float4 m4 = *(const float4*)&mask[((size_t)bb * LSEQ + q0 + r) * LSEQ + jt * 64 + c];
            *(float4*)&Ms[r * 68 + c] = m4;
        }
        __syncthreads();

        // S = Q K^T (scaled): 4 ksteps x 8 j = 32 mma
        float sacc[8][4];
        #pragma unroll
        for (int j = 0; j < 8; j++)
            #pragma unroll
            for (int r = 0; r < 4; r++) sacc[j][r] = 0.f;
        #pragma unroll
        for (int ks = 0; ks < 4; ks++) {
            #pragma unroll
            for (int j = 0; j < 8; j++) {
                uint32_t bf[2];
                bf[0] = Ks2[(j * 8 + g) * 36 + ks * 8 + t];
                bf[1] = Ks2[(j * 8 + g) * 36 + ks * 8 + t + 4];
                mma16(sacc[j], qa[ks], bf);
            }
        }

        // exp + mask + row partial sums; write P (half2 pairs along seq)
        #pragma unroll
        for (int j = 0; j < 8; j++) {
            float p0 = __expf(sacc[j][0]);
            float p1 = __expf(sacc[j][1]);
            float p2 = __expf(sacc[j][2]);
            float p3 = __expf(sacc[j][3]);
            float2 mlo = *(const float2*)&Ms[(rw + g) * 68 + j * 8 + 2 * t];
            float2 mhi = *(const float2*)&Ms[(rw + g + 8) * 68 + j * 8 + 2 * t];
            float w0 = p0 * mlo.x, w1 = p1 * mlo.y;
            float w2 = p2 * mhi.x, w3 = p3 * mhi.y;
            sa_lo += p0 + p1;  sa_hi += p2 + p3;
            sk_lo += w0 + w1;  sk_hi += w2 + w3;
            Ps2[(rw + g) * 36 + j * 4 + t]     = pack2(w0, w1);
            Ps2[(rw + g + 8) * 36 + j * 4 + t] = pack2(w2, w3);
        }
        __syncwarp();   // P is warp-private (rows rw..rw+15) — warp sync suffices

        // zacc += P @ V: 4 ksteps x 8 j = 32 mma
        #pragma unroll
        for (int ks = 0; ks < 4; ks++) {
            uint32_t pa[4];
            pa[0] = Ps2[(rw + g) * 36 + ks * 8 + t];
            pa[1] = Ps2[(rw + g + 8) * 36 + ks * 8 + t];
            pa[2] = Ps2[(rw + g) * 36 + ks * 8 + t + 4];
            pa[3] = Ps2[(rw + g + 8) * 36 + ks * 8 + t + 4];
            #pragma unroll
            for (int j = 0; j < 8; j++) {
                uint32_t bf[2];
                bf[0] = Vs2[(ks * 8 + t) * 68 + j * 8 + g];
                bf[1] = Vs2[(ks * 8 + t + 4) * 68 + j * 8 + g];
                mma16(zacc[j], pa, bf);
            }
        }
    }

    // Reduce row sums across t lanes (cols spread over t)
    #pragma unroll
    for (int d = 1; d <= 2; d <<= 1) {
        sa_lo += __shfl_xor_sync(0xffffffffu, sa_lo, d);
        sa_hi += __shfl_xor_sync(0xffffffffu, sa_hi, d);
        sk_lo += __shfl_xor_sync(0xffffffffu, sk_lo, d);
        sk_hi += __shfl_xor_sync(0xffffffffu, sk_hi, d);
    }
    float inv_lo = 1.f / (sk_lo + 1e-10f * sa_lo);
    float inv_hi = 1.f / (sk_hi + 1e-10f * sa_hi);

    size_t row_lo = (size_t)bb * LSEQ + q0 + rw + g;
    size_t row_hi = row_lo + 8;
    #pragma unroll
    for (int j = 0; j < 8; j++) {
        int dh = hh * 64 + j * 8 + 2 * t;
        float2 o0 = { zacc[j][0] * inv_lo, zacc[j][1] * inv_lo };
        float2 o1 = { zacc[j][2] * inv_hi, zacc[j][3] * inv_hi };
        *(float2*)&z[row_lo * INNER + dh] = o0;
        *(float2*)&z[row_hi * INNER + dh] = o1;
    }
}

// ---------------------------------------------------------------------------
extern "C" void kernel_launch(void* const* d_in, const int* in_sizes, int n_in,
                              void* d_out, int out_size)
{
    const float* x     = (const float*)d_in[0];  // [2,2048,1024]
    const float* mask  = (const float*)d_in[1];  // [2,2048,2048]
    const float* W_qkv = (const float*)d_in[2];  // [1024,3072]
    const float* W_out = (const float*)d_in[3];  // [1024,1024]
    const float* b_out = (const float*)d_in[4];  // [1024]
    float* out = (float*)d_out;

    const int gemm_smem = (64 * 68 + 64 * 68) * 4;   // 34816 B
    cudaFuncSetAttribute(gemm64h, cudaFuncAttributeMaxDynamicSharedMemorySize, gemm_smem);

    // QKV projection -> scatter to q/k/v (W in native [k][n] layout)
    gemm64h<<<dim3(3072 / 64, 4096 / 64), 128, gemm_smem>>>(
        x, W_qkv, nullptr, nullptr, 3072, 0);

    // Attention
    const int attn_smem = (64 * 36 + 32 * 68 + 64 * 36 + 64 * 68) * 4;  // 44544 B
    cudaFuncSetAttribute(attn_mma, cudaFuncAttributeMaxDynamicSharedMemorySize, attn_smem);
    attn_mma<<<dim3(LSEQ / 64, NB * NH), 128, attn_smem>>>(mask, g_z);

    // Output projection + bias
    gemm64h<<<dim3(1024 / 64, 4096 / 64), 128, gemm_smem>>>(
        g_z, W_out, b_out, out, 1024, 1);
}